// round 11
// baseline (speedup 1.0000x reference)
#include <cuda_runtime.h>
#include <cuda_fp16.h>
#include <cstdint>

#define B_  32
#define T_  128
#define H_  512
#define V_  32000
#define G_  2048      // 4*H
#define M4_ 4096      // B*T
#define NBR 32        // recurrence CTAs (16 units each)
#define NCTA 296      // total CTAs (148 SMs x occ 2, all co-resident)
#define NTM 32        // m-tiles (M4/128)
#define NTN 250       // n-tiles (V/128)
#define TILES (NTM * NTN)

// ---------------- device scratch ----------------
__device__ __align__(16) __half  g_Eh[V_ * H_];
__device__ __align__(16) __half  g_Wih_h[G_ * H_];
__device__ __align__(16) float   g_biasc[G_];
__device__ __align__(16) __half  g_Xe[M4_ * H_];
__device__ __align__(16) float   g_Xg[(size_t)M4_ * G_];
__device__ __align__(16) __half  g_Hall[M4_ * H_];
__device__ __align__(16) __half  g_h0h[B_ * H_];
__device__ __align__(16) int     g_tok[M4_];
__device__ unsigned g_bar;                   // recurrence-private barrier counter
__device__ __align__(128) unsigned g_step;   // published completed steps
__device__ __align__(128) unsigned g_tile;   // tile queue head

// ---------------- sync helpers ----------------
__device__ __forceinline__ void rel_add(unsigned* p) {
    asm volatile("red.release.gpu.global.add.u32 [%0], %1;" :: "l"(p), "r"(1u) : "memory");
}
__device__ __forceinline__ unsigned acq_ld(unsigned* p) {
    unsigned v;
    asm volatile("ld.acquire.gpu.global.u32 %0, [%1];" : "=r"(v) : "l"(p) : "memory");
    return v;
}
__device__ __forceinline__ void rel_st(unsigned* p, unsigned v) {
    asm volatile("st.release.gpu.global.u32 [%0], %1;" :: "l"(p), "r"(v) : "memory");
}

// ---------------- token decode (dtype sniffing) ----------------
__global__ void tok_kernel(const int* __restrict__ t32)
{
    int acc = 0;
    #pragma unroll
    for (int j = 1; j < 128; j += 2) acc |= t32[j];
    bool is64 = (acc == 0);

    int m = blockIdx.x * blockDim.x + threadIdx.x;
    if (m < M4_) {
        int t = m >> 5, b = m & 31;
        int tok = 1;
        if (t > 0) {
            int idx = b * T_ + t - 1;
            tok = is64 ? t32[2 * idx] : t32[idx];
        }
        if (tok < 0) tok = 0;
        if (tok >= V_) tok = V_ - 1;
        g_tok[m] = tok;
    }
}

// ---------------- prep ----------------
__global__ void prep_kernel(const float* __restrict__ enc,
                            const float* __restrict__ E,
                            const float* __restrict__ W_ih,
                            const float* __restrict__ b_ih,
                            const float* __restrict__ b_hh)
{
    long long stride = (long long)gridDim.x * blockDim.x;
    long long tid0 = (long long)blockIdx.x * blockDim.x + threadIdx.x;

    for (long long i = tid0; i < (long long)V_ * H_; i += stride)
        g_Eh[i] = __float2half(E[i]);
    for (long long i = tid0; i < (long long)G_ * H_; i += stride)
        g_Wih_h[i] = __float2half(W_ih[i]);
    for (long long i = tid0; i < G_; i += stride)
        g_biasc[i] = b_ih[i] + b_hh[i];
    for (long long i = tid0; i < (long long)M4_ * H_; i += stride) {
        int m = (int)(i >> 9), k = (int)(i & 511);
        int tok = g_tok[m];
        g_Xe[i] = __float2half(E[(long long)tok * H_ + k]);
    }
    for (long long i = tid0; i < B_ * H_; i += stride)
        g_h0h[i] = __float2half(enc[i]);
    if (tid0 == 0) { g_bar = 0u; g_tile = 0u; g_step = 0u; }
}

// ---------------- common PTX helpers ----------------
__device__ __forceinline__ uint32_t cvta_s(const void* p) {
    return (uint32_t)__cvta_generic_to_shared(p);
}
__device__ __forceinline__ void cp16(uint32_t d, const void* s) {
    asm volatile("cp.async.cg.shared.global [%0], [%1], 16;" :: "r"(d), "l"(s));
}
__device__ __forceinline__ void ldm4(uint32_t& r0, uint32_t& r1, uint32_t& r2, uint32_t& r3, uint32_t a) {
    asm volatile("ldmatrix.sync.aligned.m8n8.x4.shared.b16 {%0,%1,%2,%3},[%4];"
                 : "=r"(r0), "=r"(r1), "=r"(r2), "=r"(r3) : "r"(a));
}
__device__ __forceinline__ void mma16816(float* c, const uint32_t* a, const uint32_t* b) {
    asm volatile("mma.sync.aligned.m16n8k16.row.col.f32.f16.f16.f32 "
                 "{%0,%1,%2,%3},{%4,%5,%6,%7},{%8,%9},{%0,%1,%2,%3};"
                 : "+f"(c[0]), "+f"(c[1]), "+f"(c[2]), "+f"(c[3])
                 : "r"(a[0]), "r"(a[1]), "r"(a[2]), "r"(a[3]), "r"(b[0]), "r"(b[1]));
}

#define SPAD 40

// ---------------- GEMM1: Xg = Xe @ Wih^T + biasc (proven, unchanged) ----------------
__global__ __launch_bounds__(256, 2)
void hgemm1_kernel()
{
    const __half* A  = g_Xe;
    const __half* Bm = g_Wih_h;
    const int K = H_, N = G_;
    const int m0 = blockIdx.y * 128, n0 = blockIdx.x * 128;

    __shared__ __align__(16) __half As[2][128 * SPAD];
    __shared__ __align__(16) __half Bs[2][128 * SPAD];

    int tid = threadIdx.x, lane = tid & 31, warp = tid >> 5;
    int wm = warp >> 2, wn = warp & 3;

    float acc[4][4][4];
    #pragma unroll
    for (int i = 0; i < 4; i++)
        #pragma unroll
        for (int j = 0; j < 4; j++)
            #pragma unroll
            for (int v = 0; v < 4; v++) acc[i][j][v] = 0.f;

    const __half* gA = A  + (size_t)m0 * K;
    const __half* gB = Bm + (size_t)n0 * K;

    auto load_stage = [&](int s, int ko) {
        #pragma unroll
        for (int id = tid; id < 512; id += 256) {
            int r = id >> 2, c = id & 3;
            cp16(cvta_s(&As[s][r * SPAD + c * 8]), gA + (size_t)r * K + ko + c * 8);
            cp16(cvta_s(&Bs[s][r * SPAD + c * 8]), gB + (size_t)r * K + ko + c * 8);
        }
        asm volatile("cp.async.commit_group;");
    };

    load_stage(0, 0);
    #pragma unroll 1
    for (int it = 0; it < 16; ++it) {
        if (it < 15) load_stage((it + 1) & 1, (it + 1) * 32);
        else asm volatile("cp.async.commit_group;");
        asm volatile("cp.async.wait_group 1;");
        __syncthreads();
        int s = it & 1;
        #pragma unroll
        for (int kk = 0; kk < 32; kk += 16) {
            uint32_t af[4][4], bf[4][2];
            int rsel = lane & 15;
            int csel = kk + ((lane >> 4) << 3);
            #pragma unroll
            for (int mi = 0; mi < 4; mi++) {
                uint32_t a = cvta_s(&As[s][(wm * 64 + mi * 16 + rsel) * SPAD + csel]);
                ldm4(af[mi][0], af[mi][1], af[mi][2], af[mi][3], a);
            }
            #pragma unroll
            for (int p = 0; p < 2; p++) {
                uint32_t r0, r1, r2, r3;
                uint32_t a = cvta_s(&Bs[s][(wn * 32 + p * 16 + rsel) * SPAD + csel]);
                ldm4(r0, r1, r2, r3, a);
                bf[2 * p][0] = r0;     bf[2 * p][1] = r2;
                bf[2 * p + 1][0] = r1; bf[2 * p + 1][1] = r3;
            }
            #pragma unroll
            for (int mi = 0; mi < 4; mi++)
                #pragma unroll
                for (int nj = 0; nj < 4; nj++)
                    mma16816(acc[mi][nj], af[mi], bf[nj]);
        }
        __syncthreads();
    }

    int g = lane >> 2, t4 = lane & 3;
    #pragma unroll
    for (int mi = 0; mi < 4; mi++) {
        #pragma unroll
        for (int nj = 0; nj < 4; nj++) {
            int mr = m0 + wm * 64 + mi * 16 + g;
            int nc = n0 + wn * 32 + nj * 8 + t4 * 2;
            float b0v = g_biasc[nc], b1v = g_biasc[nc + 1];
            g_Xg[(size_t)mr * N + nc]           = acc[mi][nj][0] + b0v;
            g_Xg[(size_t)mr * N + nc + 1]       = acc[mi][nj][1] + b1v;
            g_Xg[(size_t)(mr + 8) * N + nc]     = acc[mi][nj][2] + b0v;
            g_Xg[(size_t)(mr + 8) * N + nc + 1] = acc[mi][nj][3] + b1v;
        }
    }
}

// ---------------- GEMM2 tile worker: K-chunk 64, double-buffered ----------------
#define SPD2 72

__device__ void gemm2_tile(char* smraw, int m0, int n0,
                           const float* __restrict__ bias, float* __restrict__ C)
{
    __half* As0 = (__half*)smraw;
    __half* Bs0 = As0 + 2 * 128 * SPD2;

    const int K = H_;
    int tid = threadIdx.x, lane = tid & 31, warp = tid >> 5;
    int wm = warp >> 2, wn = warp & 3;

    float acc[4][4][4];
    #pragma unroll
    for (int i = 0; i < 4; i++)
        #pragma unroll
        for (int j = 0; j < 4; j++)
            #pragma unroll
            for (int v = 0; v < 4; v++) acc[i][j][v] = 0.f;

    const __half* gA = g_Hall + (size_t)m0 * K;
    const __half* gB = g_Eh   + (size_t)n0 * K;

    auto load_stage = [&](int s, int ko) {
        __half* As = As0 + s * 128 * SPD2;
        __half* Bs = Bs0 + s * 128 * SPD2;
        #pragma unroll
        for (int id = tid; id < 1024; id += 256) {
            int r = id >> 3, c = id & 7;
            cp16(cvta_s(&As[r * SPD2 + c * 8]), gA + (size_t)r * K + ko + c * 8);
        }
        #pragma unroll
        for (int id = tid; id < 1024; id += 256) {
            int r = id >> 3, c = id & 7;
            cp16(cvta_s(&Bs[r * SPD2 + c * 8]), gB + (size_t)r * K + ko + c * 8);
        }
        asm volatile("cp.async.commit_group;");
    };

    load_stage(0, 0);
    #pragma unroll 1
    for (int it = 0; it < 8; ++it) {
        if (it < 7) load_stage((it + 1) & 1, (it + 1) * 64);
        else asm volatile("cp.async.commit_group;");
        asm volatile("cp.async.wait_group 1;");
        __syncthreads();
        int s = it & 1;
        __half* As = As0 + s * 128 * SPD2;
        __half* Bs = Bs0 + s * 128 * SPD2;
        #pragma unroll
        for (int kk = 0; kk < 64; kk += 16) {
            uint32_t af[4][4], bf[4][2];
            int rsel = lane & 15;
            int csel = kk + ((lane >> 4) << 3);
            #pragma unroll
            for (int mi = 0; mi < 4; mi++) {
                uint32_t a = cvta_s(&As[(wm * 64 + mi * 16 + rsel) * SPD2 + csel]);
                ldm4(af[mi][0], af[mi][1], af[mi][2], af[mi][3], a);
            }
            #pragma unroll
            for (int p = 0; p < 2; p++) {
                uint32_t r0, r1, r2, r3;
                uint32_t a = cvta_s(&Bs[(wn * 32 + p * 16 + rsel) * SPD2 + csel]);
                ldm4(r0, r1, r2, r3, a);
                bf[2 * p][0] = r0;     bf[2 * p][1] = r2;
                bf[2 * p + 1][0] = r1; bf[2 * p + 1][1] = r3;
            }
            #pragma unroll
            for (int mi = 0; mi < 4; mi++)
                #pragma unroll
                for (int nj = 0; nj < 4; nj++)
                    mma16816(acc[mi][nj], af[mi], bf[nj]);
        }
        __syncthreads();
    }

    int g = lane >> 2, t4 = lane & 3;
    #pragma unroll
    for (int mi = 0; mi < 4; mi++) {
        #pragma unroll
        for (int nj = 0; nj < 4; nj++) {
            int mr = m0 + wm * 64 + mi * 16 + g;
            int nc = n0 + wn * 32 + nj * 8 + t4 * 2;
            float b0v = bias[nc], b1v = bias[nc + 1];
            int t1 = mr >> 5, b1 = mr & 31;
            int m2 = mr + 8, t2 = m2 >> 5, b2 = m2 & 31;
            C[((size_t)b1 * T_ + t1) * V_ + nc]     = acc[mi][nj][0] + b0v;
            C[((size_t)b1 * T_ + t1) * V_ + nc + 1] = acc[mi][nj][1] + b1v;
            C[((size_t)b2 * T_ + t2) * V_ + nc]     = acc[mi][nj][2] + b0v;
            C[((size_t)b2 * T_ + t2) * V_ + nc + 1] = acc[mi][nj][3] + b1v;
        }
    }
}

// ---------------- fused: 32-CTA recurrence + 264-CTA overlapped GEMM2 ----------------
// Recurrence CTA cb owns units cb*16..cb*16+15 -> 64 gate rows (r = q*16+iu).
// Warp w = (m-half w&1, n-group w>>1): computes batch rows [16mh,16mh+16) x
// gate rows [16ng,16ng+16) over full k=512 in registers. No partials/reduce.
#define HS_STR 520
#define WS_STR 520
#define GSTR   33
#define HS_B   (32 * HS_STR * 2)                 // 33280
#define WS_B   (64 * WS_STR * 2)                 // 66560
#define GS_B   (64 * GSTR * 4)                   // 8448
#define REC_SMEM (HS_B + WS_B + GS_B)            // 108288
#define GEMM_SMEM (2 * 2 * 128 * SPD2 * 2)       // 73728
#define FUSED_SMEM (GEMM_SMEM > REC_SMEM ? GEMM_SMEM : REC_SMEM)

__global__ __launch_bounds__(256, 2)
void fused_kernel(const float* __restrict__ W_hh,
                  const float* __restrict__ enc,
                  const float* __restrict__ b_out,
                  float* __restrict__ out)
{
    extern __shared__ __align__(16) char smraw[];
    __shared__ int s_tile;

    const int tid = threadIdx.x, lane = tid & 31, w = tid >> 5;

    if (blockIdx.x < NBR) {
        // ---------------- recurrence role ----------------
        __half* Hs = (__half*)smraw;                 // 32 x 520 halfs
        __half* Ws = (__half*)(smraw + HS_B);        // 64 x 520 halfs
        float*  gs = (float*)(smraw + HS_B + WS_B);  // 64 x 33 floats

        const int cb = blockIdx.x;
        const int u0 = cb << 4;                      // first unit of this CTA

        // W rows: r = q*16+iu  ->  W_hh row q*512 + u0 + iu
        for (int i = tid; i < 64 * 512; i += 256) {
            int r = i >> 9, k = i & 511;
            int q = r >> 4, iu = r & 15;
            Ws[r * WS_STR + k] = __float2half(W_hh[(size_t)((q << 9) + u0 + iu) * H_ + k]);
        }
        // thread (b=lane, units u0+w and u0+w+8)
        float c0 = enc[lane * H_ + u0 + w];
        float c1 = enc[lane * H_ + u0 + w + 8];

        const int mh = w & 1, ng = w >> 1;
        const int rsel = lane & 15;
        const int csel0 = (lane >> 4) << 3;
        const int grp = lane >> 2, t4 = lane & 3;
        __syncthreads();

        for (int t = 0; t < T_; t++) {
            // prefetch Xg (independent of h): 4 gates x 2 units
            const float* xg = g_Xg + (size_t)(t * B_ + lane) * G_ + u0;
            float xa0 = __ldcg(xg + 0 * 512 + w),     xb0 = __ldcg(xg + 0 * 512 + w + 8);
            float xa1 = __ldcg(xg + 1 * 512 + w),     xb1 = __ldcg(xg + 1 * 512 + w + 8);
            float xa2 = __ldcg(xg + 2 * 512 + w),     xb2 = __ldcg(xg + 2 * 512 + w + 8);
            float xa3 = __ldcg(xg + 3 * 512 + w),     xb3 = __ldcg(xg + 3 * 512 + w + 8);

            const __half* hin = (t == 0) ? g_h0h : g_Hall + (size_t)(t - 1) * (B_ * H_);
            for (int i = tid; i < B_ * (H_ / 8); i += 256) {
                int b = i >> 6, k8 = i & 63;
                uint4 v = __ldcg((const uint4*)(hin + b * H_ + (k8 << 3)));
                *(uint4*)(Hs + b * HS_STR + (k8 << 3)) = v;
            }
            __syncthreads();

            // full-k accumulation: m16(mh) x n16(ng) x k512
            float acc[2][4];
            #pragma unroll
            for (int nj = 0; nj < 2; nj++)
                #pragma unroll
                for (int v = 0; v < 4; v++) acc[nj][v] = 0.f;

            #pragma unroll 4
            for (int kk = 0; kk < 512; kk += 16) {
                int csel = kk + csel0;
                uint32_t af[4], bf[2][2];
                {
                    uint32_t a = cvta_s(&Hs[(mh * 16 + rsel) * HS_STR + csel]);
                    ldm4(af[0], af[1], af[2], af[3], a);
                }
                {
                    uint32_t r0, r1, r2, r3;
                    uint32_t a = cvta_s(&Ws[(ng * 16 + rsel) * WS_STR + csel]);
                    ldm4(r0, r1, r2, r3, a);
                    bf[0][0] = r0; bf[0][1] = r2;
                    bf[1][0] = r1; bf[1][1] = r3;
                }
                mma16816(acc[0], af, bf[0]);
                mma16816(acc[1], af, bf[1]);
            }

            // write gates: gate row rbase = ng*16 + nj*8 + t4*2, batch col mh*16 + grp
            #pragma unroll
            for (int nj = 0; nj < 2; nj++) {
                int rb = ng * 16 + nj * 8 + t4 * 2;
                int bb = mh * 16 + grp;
                gs[rb * GSTR + bb]           = acc[nj][0];
                gs[(rb + 1) * GSTR + bb]     = acc[nj][1];
                gs[rb * GSTR + bb + 8]       = acc[nj][2];
                gs[(rb + 1) * GSTR + bb + 8] = acc[nj][3];
            }
            __syncthreads();

            // elementwise: b = lane, units iu = w and w+8 (rows q*16+iu)
            {
                int b = lane;
                float gi = gs[(0 * 16 + w) * GSTR + b] + xa0;
                float gf = gs[(1 * 16 + w) * GSTR + b] + xa1;
                float gg = gs[(2 * 16 + w) * GSTR + b] + xa2;
                float go = gs[(3 * 16 + w) * GSTR + b] + xa3;
                float i_ = 1.f / (1.f + __expf(-gi));
                float f_ = 1.f / (1.f + __expf(-gf));
                float gv = tanhf(gg);
                float o_ = 1.f / (1.f + __expf(-go));
                c0 = f_ * c0 + i_ * gv;
                float hv0 = o_ * tanhf(c0);

                int w8 = w + 8;
                gi = gs[(0 * 16 + w8) * GSTR + b] + xb0;
                gf = gs[(1 * 16 + w8) * GSTR + b] + xb1;
                gg = gs[(2 * 16 + w8) * GSTR + b] + xb2;
                go = gs[(3 * 16 + w8) * GSTR + b] + xb3;
                i_ = 1.f / (1.f + __expf(-gi));
                f_ = 1.f / (1.f + __expf(-gf));
                gv = tanhf(gg);
                o_ = 1.f / (1.f + __expf(-go));
                c1 = f_ * c1 + i_ * gv;
                float hv1 = o_ * tanhf(c1);

                __half* hrow = g_Hall + (size_t)(t * B_ + b) * H_ + u0;
                hrow[w]     = __float2half(hv0);
                hrow[w + 8] = __float2half(hv1);
            }
            __syncthreads();
            if (tid == 0) {
                rel_add(&g_bar);
                unsigned tgt = (unsigned)(t + 1) * NBR;
                while (acq_ld(&g_bar) < tgt) { }
                if (cb == 0) rel_st(&g_step, (unsigned)(t + 1));
            }
            __syncthreads();
        }
        // fall through: join the GEMM2 tile queue
    }

    // ---------------- GEMM2 worker role ----------------
    for (;;) {
        if (tid == 0) s_tile = (int)atomicAdd(&g_tile, 1u);
        __syncthreads();
        int tile = s_tile;
        if (tile >= TILES) break;
        int mt = tile / NTN, nt = tile % NTN;

        if (tid == 0) {
            unsigned need = (unsigned)(4 * mt + 4);
            while (acq_ld(&g_step) < need) __nanosleep(256);
        }
        __syncthreads();

        gemm2_tile(smraw, mt * 128, nt * 128, b_out, out);
        __syncthreads();
    }
}

// ---------------- launch ----------------
extern "C" void kernel_launch(void* const* d_in, const int* in_sizes, int n_in,
                              void* d_out, int out_size)
{
    const float* enc   = (const float*)d_in[0];
    const int*   tgt32 = (const int*)d_in[1];
    const float* E     = (const float*)d_in[2];
    const float* W_ih  = (const float*)d_in[3];
    const float* W_hh  = (const float*)d_in[4];
    const float* b_ih  = (const float*)d_in[5];
    const float* b_hh  = (const float*)d_in[6];
    const float* b_out = (const float*)d_in[7];
    float* out = (float*)d_out;

    tok_kernel<<<M4_ / 256, 256>>>(tgt32);
    prep_kernel<<<4096, 256>>>(enc, E, W_ih, b_ih, b_hh);

    dim3 g0(G_ / 128, M4_ / 128);
    hgemm1_kernel<<<g0, 256>>>();

    cudaFuncSetAttribute(fused_kernel,
                         cudaFuncAttributeMaxDynamicSharedMemorySize, FUSED_SMEM);
    fused_kernel<<<NCTA, 256, FUSED_SMEM>>>(W_hh, enc, b_out, out);
}

// round 15
// speedup vs baseline: 1.3987x; 1.3987x over previous
#include <cuda_runtime.h>
#include <cuda_fp16.h>
#include <cstdint>

#define B_  32
#define T_  128
#define H_  512
#define V_  32000
#define G_  2048      // 4*H
#define M4_ 4096      // B*T
#define NBR 64        // recurrence CTAs (8 units each)
#define NCTA 296      // total CTAs (148 SMs x occ 2, all co-resident)
#define NW  (NCTA - NBR)   // 232 converter/worker CTAs
#define NTM 32
#define NTN 250
#define TILES (NTM * NTN)

// ---------------- device scratch ----------------
__device__ __align__(16) __half  g_Eh[V_ * H_];
__device__ __align__(16) __half  g_Wih_h[G_ * H_];
__device__ __align__(16) float   g_biasc[G_];
__device__ __align__(16) __half  g_Xe[M4_ * H_];
__device__ __align__(16) float   g_Xg[(size_t)M4_ * G_];
__device__ __align__(16) __half  g_Hall[M4_ * H_];
__device__ __align__(16) __half  g_h0h[B_ * H_];
__device__ __align__(16) int     g_tok[M4_];
__device__ unsigned g_bar;                    // recurrence-private barrier counter
__device__ __align__(128) unsigned g_step;    // published completed steps
__device__ __align__(128) unsigned g_tile;    // tile queue head
__device__ __align__(128) unsigned g_econv;   // E-conversion completion counter

// ---------------- sync helpers ----------------
__device__ __forceinline__ void rel_add(unsigned* p) {
    asm volatile("red.release.gpu.global.add.u32 [%0], %1;" :: "l"(p), "r"(1u) : "memory");
}
__device__ __forceinline__ unsigned acq_ld(unsigned* p) {
    unsigned v;
    asm volatile("ld.acquire.gpu.global.u32 %0, [%1];" : "=r"(v) : "l"(p) : "memory");
    return v;
}
__device__ __forceinline__ void rel_st(unsigned* p, unsigned v) {
    asm volatile("st.release.gpu.global.u32 [%0], %1;" :: "l"(p), "r"(v) : "memory");
}

// ---------------- token decode (dtype sniffing) ----------------
__global__ void tok_kernel(const int* __restrict__ t32)
{
    int acc = 0;
    #pragma unroll
    for (int j = 1; j < 128; j += 2) acc |= t32[j];
    bool is64 = (acc == 0);

    int m = blockIdx.x * blockDim.x + threadIdx.x;
    if (m < M4_) {
        int t = m >> 5, b = m & 31;
        int tok = 1;
        if (t > 0) {
            int idx = b * T_ + t - 1;
            tok = is64 ? t32[2 * idx] : t32[idx];
        }
        if (tok < 0) tok = 0;
        if (tok >= V_) tok = V_ - 1;
        g_tok[m] = tok;
    }
}

// ---------------- prep (E-conversion moved into fused workers) ----------------
__global__ void prep_kernel(const float* __restrict__ enc,
                            const float* __restrict__ E,
                            const float* __restrict__ W_ih,
                            const float* __restrict__ b_ih,
                            const float* __restrict__ b_hh)
{
    long long stride = (long long)gridDim.x * blockDim.x;
    long long tid0 = (long long)blockIdx.x * blockDim.x + threadIdx.x;

    for (long long i = tid0; i < (long long)G_ * H_; i += stride)
        g_Wih_h[i] = __float2half(W_ih[i]);
    for (long long i = tid0; i < G_; i += stride)
        g_biasc[i] = b_ih[i] + b_hh[i];
    for (long long i = tid0; i < (long long)M4_ * H_; i += stride) {
        int m = (int)(i >> 9), k = (int)(i & 511);
        int tok = g_tok[m];
        g_Xe[i] = __float2half(E[(long long)tok * H_ + k]);
    }
    for (long long i = tid0; i < B_ * H_; i += stride)
        g_h0h[i] = __float2half(enc[i]);
    if (tid0 == 0) { g_bar = 0u; g_tile = 0u; g_step = 0u; g_econv = 0u; }
}

// ---------------- common PTX helpers ----------------
__device__ __forceinline__ uint32_t cvta_s(const void* p) {
    return (uint32_t)__cvta_generic_to_shared(p);
}
__device__ __forceinline__ void cp16(uint32_t d, const void* s) {
    asm volatile("cp.async.cg.shared.global [%0], [%1], 16;" :: "r"(d), "l"(s));
}
__device__ __forceinline__ void ldm4(uint32_t& r0, uint32_t& r1, uint32_t& r2, uint32_t& r3, uint32_t a) {
    asm volatile("ldmatrix.sync.aligned.m8n8.x4.shared.b16 {%0,%1,%2,%3},[%4];"
                 : "=r"(r0), "=r"(r1), "=r"(r2), "=r"(r3) : "r"(a));
}
__device__ __forceinline__ void mma16816(float* c, const uint32_t* a, const uint32_t* b) {
    asm volatile("mma.sync.aligned.m16n8k16.row.col.f32.f16.f16.f32 "
                 "{%0,%1,%2,%3},{%4,%5,%6,%7},{%8,%9},{%0,%1,%2,%3};"
                 : "+f"(c[0]), "+f"(c[1]), "+f"(c[2]), "+f"(c[3])
                 : "r"(a[0]), "r"(a[1]), "r"(a[2]), "r"(a[3]), "r"(b[0]), "r"(b[1]));
}

#define SPAD 40

// ---------------- GEMM1: Xg = Xe @ Wih^T + biasc ----------------
__global__ __launch_bounds__(256, 2)
void hgemm1_kernel()
{
    const __half* A  = g_Xe;
    const __half* Bm = g_Wih_h;
    const int K = H_, N = G_;
    const int m0 = blockIdx.y * 128, n0 = blockIdx.x * 128;

    __shared__ __align__(16) __half As[2][128 * SPAD];
    __shared__ __align__(16) __half Bs[2][128 * SPAD];

    int tid = threadIdx.x, lane = tid & 31, warp = tid >> 5;
    int wm = warp >> 2, wn = warp & 3;

    float acc[4][4][4];
    #pragma unroll
    for (int i = 0; i < 4; i++)
        #pragma unroll
        for (int j = 0; j < 4; j++)
            #pragma unroll
            for (int v = 0; v < 4; v++) acc[i][j][v] = 0.f;

    const __half* gA = A  + (size_t)m0 * K;
    const __half* gB = Bm + (size_t)n0 * K;

    auto load_stage = [&](int s, int ko) {
        #pragma unroll
        for (int id = tid; id < 512; id += 256) {
            int r = id >> 2, c = id & 3;
            cp16(cvta_s(&As[s][r * SPAD + c * 8]), gA + (size_t)r * K + ko + c * 8);
            cp16(cvta_s(&Bs[s][r * SPAD + c * 8]), gB + (size_t)r * K + ko + c * 8);
        }
        asm volatile("cp.async.commit_group;");
    };

    load_stage(0, 0);
    #pragma unroll 1
    for (int it = 0; it < 16; ++it) {
        if (it < 15) load_stage((it + 1) & 1, (it + 1) * 32);
        else asm volatile("cp.async.commit_group;");
        asm volatile("cp.async.wait_group 1;");
        __syncthreads();
        int s = it & 1;
        #pragma unroll
        for (int kk = 0; kk < 32; kk += 16) {
            uint32_t af[4][4], bf[4][2];
            int rsel = lane & 15;
            int csel = kk + ((lane >> 4) << 3);
            #pragma unroll
            for (int mi = 0; mi < 4; mi++) {
                uint32_t a = cvta_s(&As[s][(wm * 64 + mi * 16 + rsel) * SPAD + csel]);
                ldm4(af[mi][0], af[mi][1], af[mi][2], af[mi][3], a);
            }
            #pragma unroll
            for (int p = 0; p < 2; p++) {
                uint32_t r0, r1, r2, r3;
                uint32_t a = cvta_s(&Bs[s][(wn * 32 + p * 16 + rsel) * SPAD + csel]);
                ldm4(r0, r1, r2, r3, a);
                bf[2 * p][0] = r0;     bf[2 * p][1] = r2;
                bf[2 * p + 1][0] = r1; bf[2 * p + 1][1] = r3;
            }
            #pragma unroll
            for (int mi = 0; mi < 4; mi++)
                #pragma unroll
                for (int nj = 0; nj < 4; nj++)
                    mma16816(acc[mi][nj], af[mi], bf[nj]);
        }
        __syncthreads();
    }

    int g = lane >> 2, t4 = lane & 3;
    #pragma unroll
    for (int mi = 0; mi < 4; mi++) {
        #pragma unroll
        for (int nj = 0; nj < 4; nj++) {
            int mr = m0 + wm * 64 + mi * 16 + g;
            int nc = n0 + wn * 32 + nj * 8 + t4 * 2;
            float b0v = g_biasc[nc], b1v = g_biasc[nc + 1];
            g_Xg[(size_t)mr * N + nc]           = acc[mi][nj][0] + b0v;
            g_Xg[(size_t)mr * N + nc + 1]       = acc[mi][nj][1] + b1v;
            g_Xg[(size_t)(mr + 8) * N + nc]     = acc[mi][nj][2] + b0v;
            g_Xg[(size_t)(mr + 8) * N + nc + 1] = acc[mi][nj][3] + b1v;
        }
    }
}

// ---------------- GEMM2 tile worker: K-chunk 64, double-buffered ----------------
#define SPD2 72

__device__ void gemm2_tile(char* smraw, int m0, int n0,
                           const float* __restrict__ bias, float* __restrict__ C)
{
    __half* As0 = (__half*)smraw;
    __half* Bs0 = As0 + 2 * 128 * SPD2;

    const int K = H_;
    int tid = threadIdx.x, lane = tid & 31, warp = tid >> 5;
    int wm = warp >> 2, wn = warp & 3;

    float acc[4][4][4];
    #pragma unroll
    for (int i = 0; i < 4; i++)
        #pragma unroll
        for (int j = 0; j < 4; j++)
            #pragma unroll
            for (int v = 0; v < 4; v++) acc[i][j][v] = 0.f;

    const __half* gA = g_Hall + (size_t)m0 * K;
    const __half* gB = g_Eh   + (size_t)n0 * K;

    auto load_stage = [&](int s, int ko) {
        __half* As = As0 + s * 128 * SPD2;
        __half* Bs = Bs0 + s * 128 * SPD2;
        #pragma unroll
        for (int id = tid; id < 1024; id += 256) {
            int r = id >> 3, c = id & 7;
            cp16(cvta_s(&As[r * SPD2 + c * 8]), gA + (size_t)r * K + ko + c * 8);
        }
        #pragma unroll
        for (int id = tid; id < 1024; id += 256) {
            int r = id >> 3, c = id & 7;
            cp16(cvta_s(&Bs[r * SPD2 + c * 8]), gB + (size_t)r * K + ko + c * 8);
        }
        asm volatile("cp.async.commit_group;");
    };

    load_stage(0, 0);
    #pragma unroll 1
    for (int it = 0; it < 8; ++it) {
        if (it < 7) load_stage((it + 1) & 1, (it + 1) * 64);
        else asm volatile("cp.async.commit_group;");
        asm volatile("cp.async.wait_group 1;");
        __syncthreads();
        int s = it & 1;
        __half* As = As0 + s * 128 * SPD2;
        __half* Bs = Bs0 + s * 128 * SPD2;
        #pragma unroll
        for (int kk = 0; kk < 64; kk += 16) {
            uint32_t af[4][4], bf[4][2];
            int rsel = lane & 15;
            int csel = kk + ((lane >> 4) << 3);
            #pragma unroll
            for (int mi = 0; mi < 4; mi++) {
                uint32_t a = cvta_s(&As[(wm * 64 + mi * 16 + rsel) * SPD2 + csel]);
                ldm4(af[mi][0], af[mi][1], af[mi][2], af[mi][3], a);
            }
            #pragma unroll
            for (int p = 0; p < 2; p++) {
                uint32_t r0, r1, r2, r3;
                uint32_t a = cvta_s(&Bs[(wn * 32 + p * 16 + rsel) * SPD2 + csel]);
                ldm4(r0, r1, r2, r3, a);
                bf[2 * p][0] = r0;     bf[2 * p][1] = r2;
                bf[2 * p + 1][0] = r1; bf[2 * p + 1][1] = r3;
            }
            #pragma unroll
            for (int mi = 0; mi < 4; mi++)
                #pragma unroll
                for (int nj = 0; nj < 4; nj++)
                    mma16816(acc[mi][nj], af[mi], bf[nj]);
        }
        __syncthreads();
    }

    int g = lane >> 2, t4 = lane & 3;
    #pragma unroll
    for (int mi = 0; mi < 4; mi++) {
        #pragma unroll
        for (int nj = 0; nj < 4; nj++) {
            int mr = m0 + wm * 64 + mi * 16 + g;
            int nc = n0 + wn * 32 + nj * 8 + t4 * 2;
            float b0v = bias[nc], b1v = bias[nc + 1];
            int t1 = mr >> 5, b1 = mr & 31;
            int m2 = mr + 8, t2 = m2 >> 5, b2 = m2 & 31;
            C[((size_t)b1 * T_ + t1) * V_ + nc]     = acc[mi][nj][0] + b0v;
            C[((size_t)b1 * T_ + t1) * V_ + nc + 1] = acc[mi][nj][1] + b1v;
            C[((size_t)b2 * T_ + t2) * V_ + nc]     = acc[mi][nj][2] + b0v;
            C[((size_t)b2 * T_ + t2) * V_ + nc + 1] = acc[mi][nj][3] + b1v;
        }
    }
}

// ---------------- fused: 64-CTA recurrence + 232-CTA E-convert + GEMM2 ----------------
// (exact R9 recurrence: CTA cb owns units cb*8..cb*8+7, warps k-split 64,
//  partials in region aliasing the h staging buffer)
#define HS_STR 520
#define WS_STR 520
#define PSTR   33
#define REG0_B 33792
#define REC_SMEM (REG0_B + 32 * WS_STR * 2)          // 67072
#define GEMM_SMEM (2 * 2 * 128 * SPD2 * 2)           // 73728
#define FUSED_SMEM (GEMM_SMEM > REC_SMEM ? GEMM_SMEM : REC_SMEM)

__global__ __launch_bounds__(256, 2)
void fused_kernel(const float* __restrict__ W_hh,
                  const float* __restrict__ enc,
                  const float* __restrict__ E,
                  const float* __restrict__ b_out,
                  float* __restrict__ out)
{
    extern __shared__ __align__(16) char smraw[];
    __shared__ int s_tile;

    const int tid = threadIdx.x, lane = tid & 31, w = tid >> 5;

    if (blockIdx.x < NBR) {
        // ---------------- recurrence role (R9-proven) ----------------
        __half* Hs = (__half*)smraw;
        float*  P  = (float*)smraw;
        __half* Ws = (__half*)(smraw + REG0_B);

        const int cb = blockIdx.x;
        const int u0 = cb << 3;

        for (int i = tid; i < 32 * 512; i += 256) {
            int r = i >> 9, k = i & 511;
            int q = r >> 3, iu = r & 7;
            Ws[r * WS_STR + k] = __float2half(W_hh[(size_t)((q << 9) + u0 + iu) * H_ + k]);
        }
        float cst = enc[lane * H_ + u0 + w];

        const int rsel = lane & 15;
        const int csel0 = (w << 6) + ((lane >> 4) << 3);
        const int grp = lane >> 2, t4 = lane & 3;
        __syncthreads();

        for (int t = 0; t < T_; t++) {
            const float* xg = g_Xg + (size_t)(t * B_ + lane) * G_ + u0 + w;
            float x0 = __ldcg(xg);
            float x1 = __ldcg(xg + 512);
            float x2 = __ldcg(xg + 1024);
            float x3 = __ldcg(xg + 1536);

            const __half* hin = (t == 0) ? g_h0h : g_Hall + (size_t)(t - 1) * (B_ * H_);
            for (int i = tid; i < B_ * (H_ / 8); i += 256) {
                int b = i >> 6, k8 = i & 63;
                uint4 v = __ldcg((const uint4*)(hin + b * H_ + (k8 << 3)));
                *(uint4*)(Hs + b * HS_STR + (k8 << 3)) = v;
            }
            __syncthreads();

            float acc[2][4][4];
            #pragma unroll
            for (int mi = 0; mi < 2; mi++)
                #pragma unroll
                for (int nj = 0; nj < 4; nj++)
                    #pragma unroll
                    for (int v = 0; v < 4; v++) acc[mi][nj][v] = 0.f;

            #pragma unroll
            for (int kk = 0; kk < 64; kk += 16) {
                int csel = csel0 + kk;
                uint32_t af[2][4], bf[4][2];
                #pragma unroll
                for (int mi = 0; mi < 2; mi++) {
                    uint32_t a = cvta_s(&Hs[(mi * 16 + rsel) * HS_STR + csel]);
                    ldm4(af[mi][0], af[mi][1], af[mi][2], af[mi][3], a);
                }
                #pragma unroll
                for (int p = 0; p < 2; p++) {
                    uint32_t r0, r1, r2, r3;
                    uint32_t a = cvta_s(&Ws[(p * 16 + rsel) * WS_STR + csel]);
                    ldm4(r0, r1, r2, r3, a);
                    bf[2 * p][0] = r0;     bf[2 * p][1] = r2;
                    bf[2 * p + 1][0] = r1; bf[2 * p + 1][1] = r3;
                }
                #pragma unroll
                for (int mi = 0; mi < 2; mi++)
                    #pragma unroll
                    for (int nj = 0; nj < 4; nj++)
                        mma16816(acc[mi][nj], af[mi], bf[nj]);
            }
            __syncthreads();   // Hs reads done -> safe to alias P

            float* Pw = P + w * 32 * PSTR;
            #pragma unroll
            for (int mi = 0; mi < 2; mi++)
                #pragma unroll
                for (int nj = 0; nj < 4; nj++) {
                    int mbase = mi * 16 + grp, nbase = nj * 8 + t4 * 2;
                    Pw[mbase * PSTR + nbase]           = acc[mi][nj][0];
                    Pw[mbase * PSTR + nbase + 1]       = acc[mi][nj][1];
                    Pw[(mbase + 8) * PSTR + nbase]     = acc[mi][nj][2];
                    Pw[(mbase + 8) * PSTR + nbase + 1] = acc[mi][nj][3];
                }
            __syncthreads();

            {
                int b = lane;
                float s0 = 0, s1 = 0, s2 = 0, s3 = 0;
                #pragma unroll
                for (int ww = 0; ww < 8; ww++) {
                    const float* Pr = P + (ww * 32 + b) * PSTR;
                    s0 += Pr[0 * 8 + w];
                    s1 += Pr[1 * 8 + w];
                    s2 += Pr[2 * 8 + w];
                    s3 += Pr[3 * 8 + w];
                }
                float gi = s0 + x0;
                float gf = s1 + x1;
                float gg = s2 + x2;
                float go = s3 + x3;
                float i_ = 1.f / (1.f + __expf(-gi));
                float f_ = 1.f / (1.f + __expf(-gf));
                float gv = tanhf(gg);
                float o_ = 1.f / (1.f + __expf(-go));
                cst = f_ * cst + i_ * gv;
                float hv = o_ * tanhf(cst);
                g_Hall[(size_t)(t * B_ + b) * H_ + u0 + w] = __float2half(hv);
            }
            __syncthreads();
            if (tid == 0) {
                rel_add(&g_bar);
                unsigned tgt = (unsigned)(t + 1) * NBR;
                while (acq_ld(&g_bar) < tgt) { }
                if (cb == 0) rel_st(&g_step, (unsigned)(t + 1));
            }
            __syncthreads();
        }
        // fall through: join the GEMM2 tile queue
    } else {
        // ---------------- E fp32 -> fp16 conversion (workers, off critical path) ----
        int wi = blockIdx.x - NBR;
        const int nthreads = NW * 256;
        for (long long i = ((long long)wi * 256 + tid) * 4; i < (long long)V_ * H_;
             i += (long long)nthreads * 4) {
            float4 v = __ldcg((const float4*)(E + i));
            __half2 lo = __floats2half2_rn(v.x, v.y);
            __half2 hi = __floats2half2_rn(v.z, v.w);
            *(uint2*)(g_Eh + i) = make_uint2(*(uint32_t*)&lo, *(uint32_t*)&hi);
        }
        __syncthreads();
        if (tid == 0) rel_add(&g_econv);
    }

    // ---------------- GEMM2 worker role ----------------
    bool ewait = true;
    for (;;) {
        if (tid == 0) s_tile = (int)atomicAdd(&g_tile, 1u);
        __syncthreads();
        int tile = s_tile;
        if (tile >= TILES) break;
        int mt = tile / NTN, nt = tile % NTN;

        if (tid == 0) {
            if (ewait) {
                while (acq_ld(&g_econv) < (unsigned)NW) __nanosleep(64);
            }
            unsigned need = (unsigned)(4 * mt + 4);
            while (acq_ld(&g_step) < need) __nanosleep(64);
        }
        ewait = false;
        __syncthreads();

        gemm2_tile(smraw, mt * 128, nt * 128, b_out, out);
        __syncthreads();
    }
}

// ---------------- launch ----------------
extern "C" void kernel_launch(void* const* d_in, const int* in_sizes, int n_in,
                              void* d_out, int out_size)
{
    const float* enc   = (const float*)d_in[0];
    const int*   tgt32 = (const int*)d_in[1];
    const float* E     = (const float*)d_in[2];
    const float* W_ih  = (const float*)d_in[3];
    const float* W_hh  = (const float*)d_in[4];
    const float* b_ih  = (const float*)d_in[5];
    const float* b_hh  = (const float*)d_in[6];
    const float* b_out = (const float*)d_in[7];
    float* out = (float*)d_out;

    tok_kernel<<<M4_ / 256, 256>>>(tgt32);
    prep_kernel<<<2048, 256>>>(enc, E, W_ih, b_ih, b_hh);

    dim3 g0(G_ / 128, M4_ / 128);
    hgemm1_kernel<<<g0, 256>>>();

    cudaFuncSetAttribute(fused_kernel,
                         cudaFuncAttributeMaxDynamicSharedMemorySize, FUSED_SMEM);
    fused_kernel<<<NCTA, 256, FUSED_SMEM>>>(W_hh, enc, E, b_out, out);
}